// round 16
// baseline (speedup 1.0000x reference)
#include <cuda_runtime.h>
#include <cstddef>

// Problem constants (fixed by the reference)
#define B_    4096
#define NIN_  512
#define L_    16
#define N_    512
#define K_    32
#define NOUT_ 256
#define NNEUR_ (L_ * N_ + NOUT_)      // 8448 total neurons
#define MAXP_  32                     // max pairs/neuron (<= 64 entries / 2)
#define PSLOTS_ (MAXP_ + 2)           // +2 dup-last-pair slots for depth-2 prefetch

#define NSM_   148
#define LGRID_ (NSM_ * 8)             // 1184 blocks: exactly co-residency capacity

// Unified byte buffer, feature-major rows of B_ bytes:
//   rows [0, 512):        x hi-plane  (u16 value >> 8)
//   rows [512, 1024):     x lo-plane  (u16 value & 0xFF)
//   rows [1024, 9216):    hidden activations u8 = round(255*sigmoid)
#define NROWS_ (2 * NIN_ + L_ * N_)   // 9216
__device__ unsigned char g_bytes[(size_t)NROWS_ * B_];

// Per-neuron preprocessed PAIR table: slot = {off0, off1, wpacked_s16x2, 0}.
// Slots [np, PSLOTS_) duplicate the last real pair with w=0 (prefetch-safe).
__device__ int4  g_ptab [(size_t)NNEUR_ * PSLOTS_];
__device__ int   g_np   [NNEUR_];                  // pair count
__device__ float g_scale[NNEUR_];                  // s/32767
__device__ float g_badj [NNEUR_];                  // bias + offset correction

__device__ __forceinline__ float tanhapx_(float x) {
    float r; asm("tanh.approx.f32 %0, %1;" : "=f"(r) : "f"(x)); return r;
}
__device__ __forceinline__ unsigned prmt_(unsigned a, unsigned b, unsigned sel) {
    unsigned d; asm("prmt.b32 %0, %1, %2, %3;" : "=r"(d) : "r"(a), "r"(b), "r"(sel));
    return d;
}
__device__ __forceinline__ void dp2a_lo_(int& acc, int a, unsigned b) {
    asm("dp2a.lo.s32.u32 %0, %1, %2, %0;" : "+r"(acc) : "r"(a), "r"(b));
}
__device__ __forceinline__ void dp2a_hi_(int& acc, int a, unsigned b) {
    asm("dp2a.hi.s32.u32 %0, %1, %2, %0;" : "+r"(acc) : "r"(a), "r"(b));
}

// Two feature words (4 batch bytes each) + s16x2 weight -> 8 MACs.
__device__ __forceinline__ void tpair2_(int* acc, unsigned A, unsigned Bw, int w01) {
    unsigned t0 = prmt_(A, Bw, 0x5140u);   // A0,B0,A1,B1
    unsigned t1 = prmt_(A, Bw, 0x7362u);   // A2,B2,A3,B3
    dp2a_lo_(acc[0], w01, t0);
    dp2a_hi_(acc[1], w01, t0);
    dp2a_lo_(acc[2], w01, t1);
    dp2a_hi_(acc[3], w01, t1);
}

// One loaded pair: a,b = uint4 rows of two features (16 batch elems).
__device__ __forceinline__ void compute_pair_(int* iacc, uint4 a, uint4 b, int w01) {
    tpair2_(iacc + 0,  a.x, b.x, w01);
    tpair2_(iacc + 4,  a.y, b.y, w01);
    tpair2_(iacc + 8,  a.z, b.z, w01);
    tpair2_(iacc + 12, a.w, b.w, w01);
}

// Depth-2 software-pipelined gather over the fused int4 pair table.
__device__ __forceinline__ void gather_i8_(int* iacc, const int4* s_ptab,
                                           int np, int q16) {
    const char* __restrict__ gb = reinterpret_cast<const char*>(g_bytes);
    int4 e0 = s_ptab[0];
    int4 e1 = s_ptab[1];
    uint4 a0 = __ldg(reinterpret_cast<const uint4*>(gb + e0.x + q16));
    uint4 b0 = __ldg(reinterpret_cast<const uint4*>(gb + e0.y + q16));
    uint4 a1 = __ldg(reinterpret_cast<const uint4*>(gb + e1.x + q16));
    uint4 b1 = __ldg(reinterpret_cast<const uint4*>(gb + e1.y + q16));
    int w0 = e0.z, w1 = e1.z;
#pragma unroll 2
    for (int p = 0; p < np; ++p) {
        const int4 e2 = s_ptab[p + 2];
        uint4 a2 = __ldg(reinterpret_cast<const uint4*>(gb + e2.x + q16));
        uint4 b2 = __ldg(reinterpret_cast<const uint4*>(gb + e2.y + q16));
        compute_pair_(iacc, a0, b0, w0);
        a0 = a1; b0 = b1; w0 = w1;
        a1 = a2; b1 = b2; w1 = e2.z;
    }
}

// ---------------------------------------------------------------------------
// Combined pre-pass: blocks [0, PREPB_) run warp-per-neuron prep;
// blocks [PREPB_, PREPB_+TRANB_) transpose x into the two u8 planes.
// ---------------------------------------------------------------------------
#define PREPB_ ((NNEUR_ + 7) / 8)              // 1056
#define TRANB_ ((NIN_ / 32) * (B_ / 32))       // 2048

__global__ void __launch_bounds__(256) pre_kernel(
    const float* __restrict__ x,
    const int* __restrict__ idx, const float* __restrict__ W,
    const float* __restrict__ b,
    const int* __restrict__ idx_out, const float* __restrict__ W_out,
    const float* __restrict__ b_out) {
    __shared__ __align__(16) char smbuf[4224];

    if (blockIdx.x < PREPB_) {
        // ---- prep: warp per neuron ----
        int*   soff = reinterpret_cast<int*>(smbuf);            // [8][66]
        float* scf  = reinterpret_cast<float*>(smbuf + 2112);   // [8][66]
        const int lane = threadIdx.x & 31;
        const int wib  = threadIdx.x >> 5;
        const int t = blockIdx.x * 8 + wib;
        if (t >= NNEUR_) return;

        const int* ip; const float* wp; float bias;
        if (t < L_ * N_) { ip = idx + (size_t)t * K_;  wp = W + (size_t)t * K_;  bias = b[t]; }
        else { const int u = t - L_ * N_;
               ip = idx_out + (size_t)u * K_;  wp = W_out + (size_t)u * K_;  bias = b_out[u]; }

        const int   f = ip[lane];
        const float w = wp[lane];
        const bool isx = (f < NIN_);
        const int nent = isx ? 2 : 1;

        int pos = nent;
#pragma unroll
        for (int d = 1; d < 32; d <<= 1) {
            int v = __shfl_up_sync(0xFFFFFFFFu, pos, d);
            if (lane >= d) pos += v;
        }
        const int ne = __shfl_sync(0xFFFFFFFFu, pos, 31);
        pos -= nent;

        int* so = soff + wib * 66;
        float* sc = scf + wib * 66;
        if (isx) {
            so[pos]     = f * B_;           sc[pos]     = w * (1.0f / 16.0f);
            so[pos + 1] = (NIN_ + f) * B_;  sc[pos + 1] = w * (1.0f / 4096.0f);
        } else {
            so[pos] = (2 * NIN_ + (f - NIN_)) * B_;  sc[pos] = w * (1.0f / 255.0f);
        }
        __syncwarp();
        if (lane == 0 && (ne & 1)) {
            so[ne] = so[ne - 1];
            sc[ne] = 0.0f;
        }
        __syncwarp();
        const int np = (ne + 1) >> 1;

        float m = fabsf(isx ? w * (1.0f / 16.0f) : w * (1.0f / 255.0f));
#pragma unroll
        for (int d = 16; d; d >>= 1) m = fmaxf(m, __shfl_xor_sync(0xFFFFFFFFu, m, d));
        const float s = (m == 0.0f) ? 1.0f : m;
        const float inv = 32767.0f / s;

        float c = isx ? -8.0f * w : 0.0f;
#pragma unroll
        for (int d = 16; d; d >>= 1) c += __shfl_xor_sync(0xFFFFFFFFu, c, d);

#pragma unroll
        for (int base = 0; base < PSLOTS_; base += 32) {
            const int slot = base + lane;
            if (slot < PSLOTS_) {
                const int pp = min(slot, np - 1);
                int q0 = __float2int_rn(sc[2 * pp] * inv);
                int q1 = __float2int_rn(sc[2 * pp + 1] * inv);
                q0 = max(-32767, min(32767, q0));
                q1 = max(-32767, min(32767, q1));
                int4 e;
                e.x = so[2 * pp];
                e.y = so[2 * pp + 1];
                e.z = (slot < np) ? ((q1 << 16) | (q0 & 0xFFFF)) : 0;
                e.w = 0;
                g_ptab[(size_t)t * PSLOTS_ + slot] = e;
            }
        }
        if (lane == 0) {
            g_np[t]    = np;
            g_scale[t] = s / 32767.0f;
            g_badj[t]  = bias + c;
        }
    } else {
        // ---- transpose: one 32x32 tile per block, 4 rows per thread ----
        float (*tile)[33] = reinterpret_cast<float(*)[33]>(smbuf);
        const int bid2 = blockIdx.x - PREPB_;
        const int f0 = (bid2 & 15) * 32;
        const int b0 = (bid2 >> 4) * 32;
        const int tx = threadIdx.x & 31;
        const int ty8 = threadIdx.x >> 5;
#pragma unroll
        for (int r = 0; r < 4; ++r) {
            const int y = ty8 + 8 * r;
            tile[y][tx] = x[(size_t)(b0 + y) * NIN_ + (f0 + tx)];
        }
        __syncthreads();
#pragma unroll
        for (int r = 0; r < 4; ++r) {
            const int y = ty8 + 8 * r;
            const float xv = tile[tx][y];
            float vf = fminf(fmaxf((xv + 8.0f) * 4096.0f, 0.0f), 65535.0f);
            const unsigned u = __float2uint_rn(vf);
            const int f = f0 + y;
            const int bb = b0 + tx;
            g_bytes[(size_t)f * B_ + bb]          = (unsigned char)(u >> 8);
            g_bytes[(size_t)(NIN_ + f) * B_ + bb] = (unsigned char)(u & 0xFF);
        }
    }
}

// ---------------------------------------------------------------------------
// One sparse layer, placement-aware work assignment.
// 1184 blocks of 128 threads (all co-resident). class c = bid % 148 selects
// the SM (placement LUT is bid%148-based), so all 8 blocks of one class —
// i.e. all blocks on one SM — share the SAME batch chunk bx = c*8/148,
// converting cross-neuron row reuse into L1 hits. Neuron coverage is static
// and exact; surplus slots exit. Correct regardless of actual placement.
// ---------------------------------------------------------------------------
__global__ void __launch_bounds__(128, 8) layer_kernel(int l) {
    const int c    = blockIdx.x % NSM_;        // placement class (SM)
    const int slot = blockIdx.x / NSM_;        // 0..7 within class
    const int bx   = (c * 8) / NSM_;           // batch chunk for this SM
    const int cst  = (bx * NSM_ + 7) / 8;      // first class of this bx pool
    const int rank = (c - cst) * 8 + slot;     // neuron-group rank within pool
    if (rank >= N_ / 4) return;                // surplus slot

    __shared__ int4  s_ptab[4][PSLOTS_];
    __shared__ int   s_np[4];
    __shared__ float s_sc[4], s_ba[4];
    const int tx = threadIdx.x, ty = threadIdx.y;
    const int n  = rank * 4 + ty;
    const int gn = l * N_ + n;

    s_ptab[ty][tx] = g_ptab[(size_t)gn * PSLOTS_ + tx];
    if (tx < PSLOTS_ - 32)
        s_ptab[ty][32 + tx] = g_ptab[(size_t)gn * PSLOTS_ + 32 + tx];
    if (tx == 0) { s_np[ty] = g_np[gn]; s_sc[ty] = g_scale[gn]; s_ba[ty] = g_badj[gn]; }
    __syncthreads();

    const int q16 = (bx * 32 + tx) * 16;

    int iacc[16];
#pragma unroll
    for (int i = 0; i < 16; ++i) iacc[i] = 0;

    gather_i8_(iacc, s_ptab[ty], s_np[ty], q16);

    const float sc = s_sc[ty];
    const float ba = s_ba[ty];
    unsigned bytes[16];
#pragma unroll
    for (int i = 0; i < 16; ++i) {
        const float pre = fmaf((float)iacc[i], sc, ba);
        const float th  = tanhapx_(0.5f * pre);                 // sigmoid = .5+.5*tanh(v/2)
        bytes[i] = __float2uint_rn(fmaf(th, 127.5f, 127.5f));   // round(255*sigmoid)
    }
    uint4 o;
    unsigned* ow = &o.x;
#pragma unroll
    for (int i = 0; i < 4; ++i) {
        unsigned lo = __byte_perm(bytes[4 * i],     bytes[4 * i + 1], 0x0040);
        unsigned hi = __byte_perm(bytes[4 * i + 2], bytes[4 * i + 3], 0x0040);
        ow[i] = __byte_perm(lo, hi, 0x5410);
    }
    *reinterpret_cast<uint4*>(g_bytes + (size_t)(2 * NIN_ + gn) * B_ + q16) = o;
}

// ---------------------------------------------------------------------------
// Output layer. block (32,4), grid (8, 64) = 512 blocks. Exact sigmoid,
// f32 out, smem transpose so each thread stores full 16B sectors.
// ---------------------------------------------------------------------------
__global__ void __launch_bounds__(128, 8) out_kernel(float* __restrict__ out) {
    __shared__ int4  s_ptab[4][PSLOTS_];
    __shared__ int   s_np[4];
    __shared__ float s_sc[4], s_ba[4];
    __shared__ float tile[4][512];
    const int tx = threadIdx.x, ty = threadIdx.y;
    const int o0 = blockIdx.y * 4;
    const int o  = o0 + ty;
    const int gn = L_ * N_ + o;

    s_ptab[ty][tx] = g_ptab[(size_t)gn * PSLOTS_ + tx];
    if (tx < PSLOTS_ - 32)
        s_ptab[ty][32 + tx] = g_ptab[(size_t)gn * PSLOTS_ + 32 + tx];
    if (tx == 0) { s_np[ty] = g_np[gn]; s_sc[ty] = g_scale[gn]; s_ba[ty] = g_badj[gn]; }
    __syncthreads();

    const int q16 = (blockIdx.x * 32 + tx) * 16;

    int iacc[16];
#pragma unroll
    for (int i = 0; i < 16; ++i) iacc[i] = 0;

    gather_i8_(iacc, s_ptab[ty], s_np[ty], q16);

    const float sc = s_sc[ty];
    const float ba = s_ba[ty];
    const int bl = tx * 16;
#pragma unroll
    for (int i = 0; i < 16; ++i) {
        const float pre = fmaf((float)iacc[i], sc, ba);
        tile[ty][bl + i] = 1.0f / (1.0f + __expf(-pre));
    }
    __syncthreads();

    const int t = ty * 32 + tx;
    const int bbase = blockIdx.x * 512;
#pragma unroll
    for (int r = 0; r < 4; ++r) {
        const int lb = t + r * 128;
        float4 w0;
        w0.x = tile[0][lb]; w0.y = tile[1][lb]; w0.z = tile[2][lb]; w0.w = tile[3][lb];
        *reinterpret_cast<float4*>(out + (size_t)(bbase + lb) * NOUT_ + o0) = w0;
    }
}

// ---------------------------------------------------------------------------
// kernel_launch: inputs in metadata order:
//   0: x (B,NIN) f32   1: W (L,N,K) f32   2: b (L,N) f32
//   3: W_out (NOUT,K) f32   4: b_out (NOUT,) f32
//   5: idx (L,N,K) i32      6: idx_out (NOUT,K) i32
// ---------------------------------------------------------------------------
extern "C" void kernel_launch(void* const* d_in, const int* in_sizes, int n_in,
                              void* d_out, int out_size) {
    const float* x     = (const float*)d_in[0];
    const float* W     = (const float*)d_in[1];
    const float* b     = (const float*)d_in[2];
    const float* W_out = (const float*)d_in[3];
    const float* b_out = (const float*)d_in[4];
    const int*   idx     = (const int*)d_in[5];
    const int*   idx_out = (const int*)d_in[6];
    float* out = (float*)d_out;

    pre_kernel<<<PREPB_ + TRANB_, 256>>>(x, idx, W, b, idx_out, W_out, b_out);
    {
        dim3 blk(32, 4);
        for (int l = 0; l < L_; ++l) layer_kernel<<<LGRID_, blk>>>(l);
    }
    {
        dim3 blk(32, 4);
        dim3 grd(8, NOUT_ / 4);  // 512 blocks
        out_kernel<<<grd, blk>>>(out);
    }
}

// round 17
// speedup vs baseline: 1.0367x; 1.0367x over previous
#include <cuda_runtime.h>
#include <cstddef>

// Problem constants (fixed by the reference)
#define B_    4096
#define NIN_  512
#define L_    16
#define N_    512
#define K_    32
#define NOUT_ 256
#define NNEUR_ (L_ * N_ + NOUT_)      // 8448 total neurons
#define MAXP_  32                     // max pairs/neuron (<= 64 entries / 2)
#define PSLOTS_ (MAXP_ + 2)           // +2 dup-last-pair slots for depth-2 prefetch

// Unified byte buffer, feature-major rows of B_ bytes:
//   rows [0, 512):        x hi-plane  (u16 value >> 8)
//   rows [512, 1024):     x lo-plane  (u16 value & 0xFF)
//   rows [1024, 9216):    hidden activations u8 = round(255*sigmoid)
#define NROWS_ (2 * NIN_ + L_ * N_)   // 9216
__device__ unsigned char g_bytes[(size_t)NROWS_ * B_];

// Per-neuron preprocessed PAIR table: slot = {off0, off1, wpacked_s16x2, 0}.
// Slots [np, PSLOTS_) duplicate the last real pair with w=0 (prefetch-safe).
__device__ int4  g_ptab [(size_t)NNEUR_ * PSLOTS_];
__device__ int   g_np   [NNEUR_];                  // pair count
__device__ float g_scale[NNEUR_];                  // s/32767
__device__ float g_badj [NNEUR_];                  // bias + offset correction

__device__ __forceinline__ float tanhapx_(float x) {
    float r; asm("tanh.approx.f32 %0, %1;" : "=f"(r) : "f"(x)); return r;
}
__device__ __forceinline__ unsigned prmt_(unsigned a, unsigned b, unsigned sel) {
    unsigned d; asm("prmt.b32 %0, %1, %2, %3;" : "=r"(d) : "r"(a), "r"(b), "r"(sel));
    return d;
}
__device__ __forceinline__ void dp2a_lo_(int& acc, int a, unsigned b) {
    asm("dp2a.lo.s32.u32 %0, %1, %2, %0;" : "+r"(acc) : "r"(a), "r"(b));
}
__device__ __forceinline__ void dp2a_hi_(int& acc, int a, unsigned b) {
    asm("dp2a.hi.s32.u32 %0, %1, %2, %0;" : "+r"(acc) : "r"(a), "r"(b));
}

// Two feature words (4 batch bytes each) + s16x2 weight -> 8 MACs.
__device__ __forceinline__ void tpair2_(int* acc, unsigned A, unsigned Bw, int w01) {
    unsigned t0 = prmt_(A, Bw, 0x5140u);   // A0,B0,A1,B1
    unsigned t1 = prmt_(A, Bw, 0x7362u);   // A2,B2,A3,B3
    dp2a_lo_(acc[0], w01, t0);
    dp2a_hi_(acc[1], w01, t0);
    dp2a_lo_(acc[2], w01, t1);
    dp2a_hi_(acc[3], w01, t1);
}

// One loaded pair: a,b = uint4 rows of two features (16 batch elems).
__device__ __forceinline__ void compute_pair_(int* iacc, uint4 a, uint4 b, int w01) {
    tpair2_(iacc + 0,  a.x, b.x, w01);
    tpair2_(iacc + 4,  a.y, b.y, w01);
    tpair2_(iacc + 8,  a.z, b.z, w01);
    tpair2_(iacc + 12, a.w, b.w, w01);
}

// Depth-2 software-pipelined gather over the fused int4 pair table.
// Slots [np, np+2) duplicate the last real pair -> unconditional prefetch is
// an L1 hit; padded weights never consumed (loop bound np). unroll 2 removes
// rotation MOVs via register renaming.
__device__ __forceinline__ void gather_i8_(int* iacc, const int4* s_ptab,
                                           int np, int q16) {
    const char* __restrict__ gb = reinterpret_cast<const char*>(g_bytes);
    int4 e0 = s_ptab[0];
    int4 e1 = s_ptab[1];
    uint4 a0 = __ldg(reinterpret_cast<const uint4*>(gb + e0.x + q16));
    uint4 b0 = __ldg(reinterpret_cast<const uint4*>(gb + e0.y + q16));
    uint4 a1 = __ldg(reinterpret_cast<const uint4*>(gb + e1.x + q16));
    uint4 b1 = __ldg(reinterpret_cast<const uint4*>(gb + e1.y + q16));
    int w0 = e0.z, w1 = e1.z;
#pragma unroll 2
    for (int p = 0; p < np; ++p) {
        const int4 e2 = s_ptab[p + 2];
        uint4 a2 = __ldg(reinterpret_cast<const uint4*>(gb + e2.x + q16));
        uint4 b2 = __ldg(reinterpret_cast<const uint4*>(gb + e2.y + q16));
        compute_pair_(iacc, a0, b0, w0);
        a0 = a1; b0 = b1; w0 = w1;
        a1 = a2; b1 = b2; w1 = e2.z;
    }
}

// ---------------------------------------------------------------------------
// Combined pre-pass: blocks [0, PREPB_) run warp-per-neuron prep;
// blocks [PREPB_, PREPB_+TRANB_) transpose x into the two u8 planes.
// NEVER calls the PDL trigger -> the first layer kernel (which has the PDL
// attribute) still waits for full completion of this grid before starting.
// ---------------------------------------------------------------------------
#define PREPB_ ((NNEUR_ + 7) / 8)              // 1056
#define TRANB_ ((NIN_ / 32) * (B_ / 32))       // 2048

__global__ void __launch_bounds__(256) pre_kernel(
    const float* __restrict__ x,
    const int* __restrict__ idx, const float* __restrict__ W,
    const float* __restrict__ b,
    const int* __restrict__ idx_out, const float* __restrict__ W_out,
    const float* __restrict__ b_out) {
    __shared__ __align__(16) char smbuf[4224];

    if (blockIdx.x < PREPB_) {
        // ---- prep: warp per neuron ----
        int*   soff = reinterpret_cast<int*>(smbuf);            // [8][66]
        float* scf  = reinterpret_cast<float*>(smbuf + 2112);   // [8][66]
        const int lane = threadIdx.x & 31;
        const int wib  = threadIdx.x >> 5;
        const int t = blockIdx.x * 8 + wib;
        if (t >= NNEUR_) return;

        const int* ip; const float* wp; float bias;
        if (t < L_ * N_) { ip = idx + (size_t)t * K_;  wp = W + (size_t)t * K_;  bias = b[t]; }
        else { const int u = t - L_ * N_;
               ip = idx_out + (size_t)u * K_;  wp = W_out + (size_t)u * K_;  bias = b_out[u]; }

        const int   f = ip[lane];
        const float w = wp[lane];
        const bool isx = (f < NIN_);
        const int nent = isx ? 2 : 1;

        int pos = nent;
#pragma unroll
        for (int d = 1; d < 32; d <<= 1) {
            int v = __shfl_up_sync(0xFFFFFFFFu, pos, d);
            if (lane >= d) pos += v;
        }
        const int ne = __shfl_sync(0xFFFFFFFFu, pos, 31);
        pos -= nent;

        int* so = soff + wib * 66;
        float* sc = scf + wib * 66;
        if (isx) {
            so[pos]     = f * B_;           sc[pos]     = w * (1.0f / 16.0f);
            so[pos + 1] = (NIN_ + f) * B_;  sc[pos + 1] = w * (1.0f / 4096.0f);
        } else {
            so[pos] = (2 * NIN_ + (f - NIN_)) * B_;  sc[pos] = w * (1.0f / 255.0f);
        }
        __syncwarp();
        if (lane == 0 && (ne & 1)) {
            so[ne] = so[ne - 1];
            sc[ne] = 0.0f;
        }
        __syncwarp();
        const int np = (ne + 1) >> 1;

        float m = fabsf(isx ? w * (1.0f / 16.0f) : w * (1.0f / 255.0f));
#pragma unroll
        for (int d = 16; d; d >>= 1) m = fmaxf(m, __shfl_xor_sync(0xFFFFFFFFu, m, d));
        const float s = (m == 0.0f) ? 1.0f : m;
        const float inv = 32767.0f / s;

        float c = isx ? -8.0f * w : 0.0f;
#pragma unroll
        for (int d = 16; d; d >>= 1) c += __shfl_xor_sync(0xFFFFFFFFu, c, d);

#pragma unroll
        for (int base = 0; base < PSLOTS_; base += 32) {
            const int slot = base + lane;
            if (slot < PSLOTS_) {
                const int pp = min(slot, np - 1);
                int q0 = __float2int_rn(sc[2 * pp] * inv);
                int q1 = __float2int_rn(sc[2 * pp + 1] * inv);
                q0 = max(-32767, min(32767, q0));
                q1 = max(-32767, min(32767, q1));
                int4 e;
                e.x = so[2 * pp];
                e.y = so[2 * pp + 1];
                e.z = (slot < np) ? ((q1 << 16) | (q0 & 0xFFFF)) : 0;
                e.w = 0;
                g_ptab[(size_t)t * PSLOTS_ + slot] = e;
            }
        }
        if (lane == 0) {
            g_np[t]    = np;
            g_scale[t] = s / 32767.0f;
            g_badj[t]  = bias + c;
        }
    } else {
        // ---- transpose: one 32x32 tile per block, 4 rows per thread ----
        float (*tile)[33] = reinterpret_cast<float(*)[33]>(smbuf);
        const int bid2 = blockIdx.x - PREPB_;
        const int f0 = (bid2 & 15) * 32;
        const int b0 = (bid2 >> 4) * 32;
        const int tx = threadIdx.x & 31;
        const int ty8 = threadIdx.x >> 5;
#pragma unroll
        for (int r = 0; r < 4; ++r) {
            const int y = ty8 + 8 * r;
            tile[y][tx] = x[(size_t)(b0 + y) * NIN_ + (f0 + tx)];
        }
        __syncthreads();
#pragma unroll
        for (int r = 0; r < 4; ++r) {
            const int y = ty8 + 8 * r;
            const float xv = tile[tx][y];
            float vf = fminf(fmaxf((xv + 8.0f) * 4096.0f, 0.0f), 65535.0f);
            const unsigned u = __float2uint_rn(vf);
            const int f = f0 + y;
            const int bb = b0 + tx;
            g_bytes[(size_t)f * B_ + bb]          = (unsigned char)(u >> 8);
            g_bytes[(size_t)(NIN_ + f) * B_ + bb] = (unsigned char)(u & 0xFF);
        }
    }
}

// ---------------------------------------------------------------------------
// One sparse layer, PDL-enabled. block (32,4): warp = one neuron, 32 tx x 16
// batch = 512. grid (8, 128) = 1024 blocks (R15 shape).
// Trigger at entry lets the NEXT kernel launch and stage its tables (which
// read only g_ptab -> written by pre_kernel, complete before layer 0) while
// this layer gathers; the dependent's gridDependencySynchronize() gates its
// g_bytes reads on this grid's full completion.
// ---------------------------------------------------------------------------
__global__ void __launch_bounds__(128, 8) layer_kernel(int l) {
    cudaTriggerProgrammaticLaunchCompletion();

    __shared__ int4  s_ptab[4][PSLOTS_];
    __shared__ int   s_np[4];
    __shared__ float s_sc[4], s_ba[4];
    const int tx = threadIdx.x, ty = threadIdx.y;
    const int n  = blockIdx.y * 4 + ty;
    const int gn = l * N_ + n;

    s_ptab[ty][tx] = g_ptab[(size_t)gn * PSLOTS_ + tx];
    if (tx < PSLOTS_ - 32)
        s_ptab[ty][32 + tx] = g_ptab[(size_t)gn * PSLOTS_ + 32 + tx];
    if (tx == 0) { s_np[ty] = g_np[gn]; s_sc[ty] = g_scale[gn]; s_ba[ty] = g_badj[gn]; }
    __syncthreads();

    cudaGridDependencySynchronize();   // previous layer's g_bytes writes visible

    const int q16 = (blockIdx.x * 32 + tx) * 16;

    int iacc[16];
#pragma unroll
    for (int i = 0; i < 16; ++i) iacc[i] = 0;

    gather_i8_(iacc, s_ptab[ty], s_np[ty], q16);

    const float sc = s_sc[ty];
    const float ba = s_ba[ty];
    unsigned bytes[16];
#pragma unroll
    for (int i = 0; i < 16; ++i) {
        const float pre = fmaf((float)iacc[i], sc, ba);
        const float th  = tanhapx_(0.5f * pre);                 // sigmoid = .5+.5*tanh(v/2)
        bytes[i] = __float2uint_rn(fmaf(th, 127.5f, 127.5f));   // round(255*sigmoid)
    }
    uint4 o;
    unsigned* ow = &o.x;
#pragma unroll
    for (int i = 0; i < 4; ++i) {
        unsigned lo = __byte_perm(bytes[4 * i],     bytes[4 * i + 1], 0x0040);
        unsigned hi = __byte_perm(bytes[4 * i + 2], bytes[4 * i + 3], 0x0040);
        ow[i] = __byte_perm(lo, hi, 0x5410);
    }
    *reinterpret_cast<uint4*>(g_bytes + (size_t)(2 * NIN_ + gn) * B_ + q16) = o;
}

// ---------------------------------------------------------------------------
// Output layer, PDL-enabled. block (32,4), grid (8, 64) = 512 blocks.
// Exact sigmoid, f32 out, smem transpose for 16B-sector stores.
// ---------------------------------------------------------------------------
__global__ void __launch_bounds__(128, 8) out_kernel(float* __restrict__ out) {
    __shared__ int4  s_ptab[4][PSLOTS_];
    __shared__ int   s_np[4];
    __shared__ float s_sc[4], s_ba[4];
    __shared__ float tile[4][512];
    const int tx = threadIdx.x, ty = threadIdx.y;
    const int o0 = blockIdx.y * 4;
    const int o  = o0 + ty;
    const int gn = L_ * N_ + o;

    s_ptab[ty][tx] = g_ptab[(size_t)gn * PSLOTS_ + tx];
    if (tx < PSLOTS_ - 32)
        s_ptab[ty][32 + tx] = g_ptab[(size_t)gn * PSLOTS_ + 32 + tx];
    if (tx == 0) { s_np[ty] = g_np[gn]; s_sc[ty] = g_scale[gn]; s_ba[ty] = g_badj[gn]; }
    __syncthreads();

    cudaGridDependencySynchronize();   // last layer's g_bytes writes visible

    const int q16 = (blockIdx.x * 32 + tx) * 16;

    int iacc[16];
#pragma unroll
    for (int i = 0; i < 16; ++i) iacc[i] = 0;

    gather_i8_(iacc, s_ptab[ty], s_np[ty], q16);

    const float sc = s_sc[ty];
    const float ba = s_ba[ty];
    const int bl = tx * 16;
#pragma unroll
    for (int i = 0; i < 16; ++i) {
        const float pre = fmaf((float)iacc[i], sc, ba);
        tile[ty][bl + i] = 1.0f / (1.0f + __expf(-pre));
    }
    __syncthreads();

    const int t = ty * 32 + tx;
    const int bbase = blockIdx.x * 512;
#pragma unroll
    for (int r = 0; r < 4; ++r) {
        const int lb = t + r * 128;
        float4 w0;
        w0.x = tile[0][lb]; w0.y = tile[1][lb]; w0.z = tile[2][lb]; w0.w = tile[3][lb];
        *reinterpret_cast<float4*>(out + (size_t)(bbase + lb) * NOUT_ + o0) = w0;
    }
}

// ---------------------------------------------------------------------------
// kernel_launch: inputs in metadata order:
//   0: x (B,NIN) f32   1: W (L,N,K) f32   2: b (L,N) f32
//   3: W_out (NOUT,K) f32   4: b_out (NOUT,) f32
//   5: idx (L,N,K) i32      6: idx_out (NOUT,K) i32
// ---------------------------------------------------------------------------
extern "C" void kernel_launch(void* const* d_in, const int* in_sizes, int n_in,
                              void* d_out, int out_size) {
    const float* x     = (const float*)d_in[0];
    const float* W     = (const float*)d_in[1];
    const float* b     = (const float*)d_in[2];
    const float* W_out = (const float*)d_in[3];
    const float* b_out = (const float*)d_in[4];
    const int*   idx     = (const int*)d_in[5];
    const int*   idx_out = (const int*)d_in[6];
    float* out = (float*)d_out;

    // pre-pass: normal launch (never triggers -> layer 0 waits for completion)
    pre_kernel<<<PREPB_ + TRANB_, 256>>>(x, idx, W, b, idx_out, W_out, b_out);

    // PDL launch config for the layer chain + output kernel
    cudaLaunchAttribute attrs[1];
    attrs[0].id = cudaLaunchAttributeProgrammaticStreamSerialization;
    attrs[0].val.programmaticStreamSerializationAllowed = 1;

    {
        cudaLaunchConfig_t cfg = {};
        cfg.gridDim  = dim3(8, N_ / 4);   // 1024 blocks
        cfg.blockDim = dim3(32, 4);
        cfg.stream   = 0;
        cfg.attrs    = attrs;
        cfg.numAttrs = 1;
        for (int l = 0; l < L_; ++l)
            cudaLaunchKernelEx(&cfg, layer_kernel, l);
    }
    {
        cudaLaunchConfig_t cfg = {};
        cfg.gridDim  = dim3(8, NOUT_ / 4);  // 512 blocks
        cfg.blockDim = dim3(32, 4);
        cfg.stream   = 0;
        cfg.attrs    = attrs;
        cfg.numAttrs = 1;
        cudaLaunchKernelEx(&cfg, out_kernel, out);
    }
}